// round 4
// baseline (speedup 1.0000x reference)
#include <cuda_runtime.h>
#include <cuda_bf16.h>
#include <cstdint>

#define NN 512
#define TT 32
#define DD 1024
#define HH 1024
#define GG 4096   // 4*H
#define KK 3072   // H + H + D

// ---------------- scratch (device globals; no allocation allowed) -------------
__device__ float g_h[NN * HH];
__device__ float g_c[NN * HH];
__device__ __align__(256) __nv_bfloat16 g_hhi[NN * HH], g_hlo[NN * HH];
__device__ __align__(256) __nv_bfloat16 g_ahi[NN * HH], g_alo[NN * HH];
__device__ __align__(256) __nv_bfloat16 g_xhi[(size_t)NN * TT * DD], g_xlo[(size_t)NN * TT * DD];
// W^T, gate-interleaved columns: row p = j*4 + gate  (gate = orig_col>>10, j = orig_col&1023)
__device__ __align__(256) __nv_bfloat16 g_wthi[(size_t)GG * KK], g_wtlo[(size_t)GG * KK];

// ---------------- small helpers ------------------------------------------------
__device__ __forceinline__ uint32_t smem_u32(const void* p) {
    uint32_t a;
    asm("{ .reg .u64 t; cvta.to.shared.u64 t, %1; cvt.u32.u64 %0, t; }" : "=r"(a) : "l"(p));
    return a;
}
__device__ __forceinline__ void cp16(uint32_t dst, const void* src) {
    asm volatile("cp.async.cg.shared.global [%0], [%1], 16;" :: "r"(dst), "l"(src));
}
__device__ __forceinline__ void cp_commit() { asm volatile("cp.async.commit_group;" ::: "memory"); }
template <int N> __device__ __forceinline__ void cp_wait() {
    asm volatile("cp.async.wait_group %0;" :: "n"(N) : "memory");
}
__device__ __forceinline__ void split_bf16(float w, __nv_bfloat16& hi, __nv_bfloat16& lo) {
    hi = __float2bfloat16(w);
    lo = __float2bfloat16(w - __bfloat162float(hi));
}
__device__ __forceinline__ void ldsm4(uint32_t& r0, uint32_t& r1, uint32_t& r2, uint32_t& r3,
                                      uint32_t addr) {
    asm volatile("ldmatrix.sync.aligned.m8n8.x4.shared.b16 {%0,%1,%2,%3}, [%4];"
                 : "=r"(r0), "=r"(r1), "=r"(r2), "=r"(r3) : "r"(addr));
}
__device__ __forceinline__ void mma16816(float* d, const uint32_t* a, uint32_t b0, uint32_t b1) {
    asm volatile(
        "mma.sync.aligned.m16n8k16.row.col.f32.bf16.bf16.f32 "
        "{%0,%1,%2,%3}, {%4,%5,%6,%7}, {%8,%9}, {%0,%1,%2,%3};"
        : "+f"(d[0]), "+f"(d[1]), "+f"(d[2]), "+f"(d[3])
        : "r"(a[0]), "r"(a[1]), "r"(a[2]), "r"(a[3]), "r"(b0), "r"(b1));
}

// ---------------- one-time prep kernels ----------------------------------------
// Transpose + hi/lo split + gate-interleave of [Wh; Wattn; Wx] -> W^T [4096][3072]
__global__ void prep_w(const float* __restrict__ Wx, const float* __restrict__ Wh,
                       const float* __restrict__ Wattn) {
    __shared__ float tile[32][33];
    int k0 = blockIdx.x * 32, n0 = blockIdx.y * 32;
#pragma unroll
    for (int dy = 0; dy < 32; dy += 8) {
        int k = k0 + threadIdx.y + dy;
        int n = n0 + threadIdx.x;
        const float* W;
        int kk = k;
        if (k < 1024)       { W = Wh; }
        else if (k < 2048)  { W = Wattn; kk = k - 1024; }
        else                { W = Wx;    kk = k - 2048; }
        tile[threadIdx.y + dy][threadIdx.x] = W[(size_t)kk * GG + n];
    }
    __syncthreads();
#pragma unroll
    for (int dy = 0; dy < 32; dy += 8) {
        int n = n0 + threadIdx.y + dy;
        int k = k0 + threadIdx.x;
        float w = tile[threadIdx.x][threadIdx.y + dy];
        __nv_bfloat16 hi, lo;
        split_bf16(w, hi, lo);
        int p = ((n & 1023) << 2) | (n >> 10);       // gate-interleaved column
        g_wthi[(size_t)p * KK + k] = hi;
        g_wtlo[(size_t)p * KK + k] = lo;
    }
}

__global__ void prep_x(const float* __restrict__ x) {
    size_t i = (size_t)blockIdx.x * 256 + threadIdx.x;
    __nv_bfloat16 hi, lo;
    split_bf16(x[i], hi, lo);
    g_xhi[i] = hi;
    g_xlo[i] = lo;
}

// ---------------- init: h0 = c0 = mean over the 16 spatial cells ---------------
__global__ void init_kernel(const float* __restrict__ A) {
    int idx = blockIdx.x * 256 + threadIdx.x;
    const float4* a4 = (const float4*)(A + (size_t)idx * 16);
    float4 a0 = a4[0], a1 = a4[1], a2 = a4[2], a3 = a4[3];
    float s = ((a0.x + a0.y) + (a0.z + a0.w)) + ((a1.x + a1.y) + (a1.z + a1.w))
            + ((a2.x + a2.y) + (a2.z + a2.w)) + ((a3.x + a3.y) + (a3.z + a3.w));
    s *= (1.0f / 16.0f);
    g_h[idx] = s;
    g_c[idx] = s;
    __nv_bfloat16 hi, lo;
    split_bf16(s, hi, lo);
    g_hhi[idx] = hi;
    g_hlo[idx] = lo;
}

// ---------------- attention over 16 spatial cells (A cached in smem) -----------
#define ATTN_SMEM (1024 * 20 * 4)   // 1024 rows x 16 floats padded to 20 (80 KB)
__global__ __launch_bounds__(256) void attn_kernel(const float* __restrict__ A) {
    extern __shared__ char dynsmem[];
    float* sA = (float*)dynsmem;
    int n = blockIdx.x;
    int tid = threadIdx.x;
    const float* Af = A + (size_t)n * HH * 16;
    const float* hp = g_h + (size_t)n * HH;

    // cache A[n] once (64 KB) into padded smem
    uint32_t sA_u = smem_u32(sA);
    for (int i = tid; i < 4096; i += 256) {
        int row = i >> 2, c = i & 3;
        cp16(sA_u + (uint32_t)(row * 20 + c * 4) * 4, Af + row * 16 + c * 4);
    }
    cp_commit();
    cp_wait<0>();
    __syncthreads();

    float part[16];
#pragma unroll
    for (int k = 0; k < 16; ++k) part[k] = 0.0f;

    for (int j = tid; j < HH; j += 256) {
        float hv = hp[j];
        const float4* a4 = (const float4*)(sA + j * 20);
        float4 a;
        a = a4[0]; part[0]  += hv * a.x; part[1]  += hv * a.y; part[2]  += hv * a.z; part[3]  += hv * a.w;
        a = a4[1]; part[4]  += hv * a.x; part[5]  += hv * a.y; part[6]  += hv * a.z; part[7]  += hv * a.w;
        a = a4[2]; part[8]  += hv * a.x; part[9]  += hv * a.y; part[10] += hv * a.z; part[11] += hv * a.w;
        a = a4[3]; part[12] += hv * a.x; part[13] += hv * a.y; part[14] += hv * a.z; part[15] += hv * a.w;
    }
#pragma unroll
    for (int k = 0; k < 16; ++k)
#pragma unroll
        for (int off = 16; off; off >>= 1)
            part[k] += __shfl_xor_sync(0xffffffffu, part[k], off);

    __shared__ float sred[8][16];
    __shared__ float sM[16];
    int warp = tid >> 5, lane = tid & 31;
    if (lane == 0) {
#pragma unroll
        for (int k = 0; k < 16; ++k) sred[warp][k] = part[k];
    }
    __syncthreads();

    if (tid < 32) {
        int k = lane & 15;
        float s = 0.0f;
#pragma unroll
        for (int w = 0; w < 8; ++w) s += sred[w][k];
        s *= (1.0f / 32.0f);                         // / sqrt(H)
        float m = s;
#pragma unroll
        for (int off = 8; off; off >>= 1) m = fmaxf(m, __shfl_xor_sync(0xffffffffu, m, off));
        float e = expf(s - m);
        float sum = e;
#pragma unroll
        for (int off = 8; off; off >>= 1) sum += __shfl_xor_sync(0xffffffffu, sum, off);
        if (lane < 16) sM[lane] = e / sum;
    }
    __syncthreads();

    for (int j = tid; j < HH; j += 256) {
        const float4* a4 = (const float4*)(sA + j * 20);
        float s = 0.0f;
        float4 a;
        a = a4[0]; s += a.x * sM[0]  + a.y * sM[1]  + a.z * sM[2]  + a.w * sM[3];
        a = a4[1]; s += a.x * sM[4]  + a.y * sM[5]  + a.z * sM[6]  + a.w * sM[7];
        a = a4[2]; s += a.x * sM[8]  + a.y * sM[9]  + a.z * sM[10] + a.w * sM[11];
        a = a4[3]; s += a.x * sM[12] + a.y * sM[13] + a.z * sM[14] + a.w * sM[15];
        size_t idx = (size_t)n * HH + j;
        __nv_bfloat16 hi, lo;
        split_bf16(s, hi, lo);
        g_ahi[idx] = hi;
        g_alo[idx] = lo;
    }
}

// ---------------- HMMA GEMM + fused gates --------------------------------------
// v = [h | attn | x_t] @ W^T(perm); M=512, N(perm)=4096, K=3072; bf16x3 split.
// CTA 128x128, 8 warps (4m x 2n), 3-stage cp.async pipeline, gate epilogue.
#define STAGE_BYTES 65536
#define A_HI_OFF 0
#define A_LO_OFF 16384
#define B_HI_OFF 32768
#define B_LO_OFF 49152
#define GEMM_SMEM (3 * STAGE_BYTES)
#define NKT 48

__global__ __launch_bounds__(256, 1) void gemm_kernel(const float* __restrict__ b,
                                                      float* __restrict__ out, int t) {
    extern __shared__ char dynsmem[];
    uint32_t sb = smem_u32(dynsmem);
    const int tid = threadIdx.x;
    const int wid = tid >> 5;
    const int lane = tid & 31;
    const int wm = wid & 3;
    const int wn = wid >> 2;
    const int m0 = blockIdx.y * 128;
    const int n0 = blockIdx.x * 128;

    float acc[2][8][4];
#pragma unroll
    for (int i = 0; i < 2; ++i)
#pragma unroll
        for (int g = 0; g < 8; ++g)
#pragma unroll
            for (int r = 0; r < 4; ++r) acc[i][g][r] = 0.0f;

    const uint32_t swb   = (lane & 7) << 4;
    const uint32_t aRow  = (uint32_t)(wm * 32 + (lane & 15)) * 128;
    const uint32_t aHalf = (uint32_t)(lane >> 4);
    const uint32_t bRow  = (uint32_t)(wn * 64 + (lane & 7) + ((lane >> 4) << 3)) * 128;
    const uint32_t bHalf = (uint32_t)((lane >> 3) & 1);

    auto load_tile = [&](int kt, int stage) {
        uint32_t base = sb + stage * STAGE_BYTES;
        const __nv_bfloat16 *ahi, *alo;
        size_t astr, akoff;
        if (kt < 16)      { ahi = g_hhi; alo = g_hlo; astr = HH; akoff = (size_t)kt * 64; }
        else if (kt < 32) { ahi = g_ahi; alo = g_alo; astr = HH; akoff = (size_t)(kt - 16) * 64; }
        else              { ahi = g_xhi; alo = g_xlo; astr = (size_t)TT * DD;
                            akoff = (size_t)t * DD + (size_t)(kt - 32) * 64; }
        size_t bkoff = (size_t)kt * 64;
#pragma unroll
        for (int i = 0; i < 4; ++i) {
            int c = tid + i * 256;
            int row = c >> 3, c16 = c & 7;
            uint32_t off = row * 128 + c16 * 16;
            uint32_t sw = off ^ ((off >> 3) & 0x70);
            size_t aoff = (size_t)(m0 + row) * astr + akoff + (size_t)c16 * 8;
            size_t boff = (size_t)(n0 + row) * KK + bkoff + (size_t)c16 * 8;
            cp16(base + A_HI_OFF + sw, ahi + aoff);
            cp16(base + A_LO_OFF + sw, alo + aoff);
            cp16(base + B_HI_OFF + sw, g_wthi + boff);
            cp16(base + B_LO_OFF + sw, g_wtlo + boff);
        }
    };

    load_tile(0, 0); cp_commit();
    load_tile(1, 1); cp_commit();

    for (int kt = 0; kt < NKT; ++kt) {
        cp_wait<1>();                 // stage kt resident
        __syncthreads();              // all warps done reading stage (kt-1)%3

        if (kt + 2 < NKT) load_tile(kt + 2, (kt + 2) % 3);
        cp_commit();

        uint32_t base = sb + (kt % 3) * STAGE_BYTES;
        uint32_t ah_base = base + A_HI_OFF, al_base = base + A_LO_OFF;
        uint32_t bh_base = base + B_HI_OFF, bl_base = base + B_LO_OFF;

#pragma unroll
        for (int q = 0; q < 4; ++q) {
            uint32_t aChunk = ((2 * q + aHalf) << 4) ^ swb;
            uint32_t bChunk = ((2 * q + bHalf) << 4) ^ swb;

            uint32_t ahf[2][4], alf[2][4];
#pragma unroll
            for (int i = 0; i < 2; ++i) {
                uint32_t ao = aRow + (uint32_t)i * 2048 + aChunk;
                ldsm4(ahf[i][0], ahf[i][1], ahf[i][2], ahf[i][3], ah_base + ao);
                ldsm4(alf[i][0], alf[i][1], alf[i][2], alf[i][3], al_base + ao);
            }
            uint32_t bhf[4][4], blf[4][4];
#pragma unroll
            for (int p = 0; p < 4; ++p) {
                uint32_t bo = bRow + (uint32_t)p * 2048 + bChunk;
                ldsm4(bhf[p][0], bhf[p][1], bhf[p][2], bhf[p][3], bh_base + bo);
                ldsm4(blf[p][0], blf[p][1], blf[p][2], blf[p][3], bl_base + bo);
            }
#pragma unroll
            for (int i = 0; i < 2; ++i)
#pragma unroll
                for (int g = 0; g < 8; ++g) {
                    uint32_t b0h = bhf[g >> 1][(g & 1) * 2], b1h = bhf[g >> 1][(g & 1) * 2 + 1];
                    uint32_t b0l = blf[g >> 1][(g & 1) * 2], b1l = blf[g >> 1][(g & 1) * 2 + 1];
                    mma16816(acc[i][g], ahf[i], b0h, b1h);   // hi*hi
                    mma16816(acc[i][g], ahf[i], b0l, b1l);   // hi*lo
                    mma16816(acc[i][g], alf[i], b0h, b1h);   // lo*hi
                }
        }
    }

    // -------- fused gate epilogue --------
    __syncthreads();                               // pipeline drained; smem reusable
    float* sv = (float*)dynsmem;                   // staging: 128 rows x 132 (padded)

    const int col0 = wn * 64 + (lane & 3) * 2;
#pragma unroll
    for (int i = 0; i < 2; ++i) {
        int r0 = wm * 32 + i * 16 + (lane >> 2);
#pragma unroll
        for (int g = 0; g < 8; ++g) {
            int c = col0 + g * 8;
            *(float2*)&sv[r0 * 132 + c]       = make_float2(acc[i][g][0], acc[i][g][1]);
            *(float2*)&sv[(r0 + 8) * 132 + c] = make_float2(acc[i][g][2], acc[i][g][3]);
        }
    }
    __syncthreads();

    const int jb = n0 >> 2;                        // this CTA's 32-wide j block
    for (int cell = tid; cell < 4096; cell += 256) {
        int row = cell >> 5, jj = cell & 31;
        float4 vv = *(const float4*)&sv[row * 132 + jj * 4];
        int j = jb + jj;
        float vi = vv.x + b[j];
        float vf = vv.y + b[j + 1024];
        float vo = vv.z + b[j + 2048];
        float vg = vv.w + b[j + 3072];
        float ig = 1.0f / (1.0f + expf(-vi));
        float fg = 1.0f / (1.0f + expf(-vf));
        float og = 1.0f / (1.0f + expf(-vo));
        float gg = tanhf(vg);
        size_t idx = (size_t)(m0 + row) * HH + j;
        float c = fg * g_c[idx] + ig * gg;
        float h = og * tanhf(c);
        g_c[idx] = c;
        g_h[idx] = h;
        __nv_bfloat16 hi, lo;
        split_bf16(h, hi, lo);
        g_hhi[idx] = hi;
        g_hlo[idx] = lo;
        out[(size_t)(m0 + row) * (TT * HH) + (size_t)t * HH + j] = h;
    }
}

// ---------------- launch ---------------------------------------------------------
extern "C" void kernel_launch(void* const* d_in, const int* in_sizes, int n_in,
                              void* d_out, int out_size) {
    const float* x     = (const float*)d_in[0];   // (N, T, D)
    const float* A     = (const float*)d_in[1];   // (N, H, 4, 4)
    const float* Wx    = (const float*)d_in[2];   // (D, 4H)
    const float* Wh    = (const float*)d_in[3];   // (H, 4H)
    const float* Wattn = (const float*)d_in[4];   // (H, 4H)
    const float* b     = (const float*)d_in[5];   // (4H,)
    float* out = (float*)d_out;                   // (N, T, H)

    cudaFuncSetAttribute(gemm_kernel, cudaFuncAttributeMaxDynamicSharedMemorySize, GEMM_SMEM);
    cudaFuncSetAttribute(attn_kernel, cudaFuncAttributeMaxDynamicSharedMemorySize, ATTN_SMEM);

    prep_w<<<dim3(KK / 32, GG / 32), dim3(32, 8)>>>(Wx, Wh, Wattn);
    prep_x<<<(NN * TT * DD) / 256, 256>>>(x);
    init_kernel<<<(NN * HH) / 256, 256>>>(A);
    for (int t = 0; t < TT; ++t) {
        attn_kernel<<<NN, 256, ATTN_SMEM>>>(A);
        gemm_kernel<<<dim3(GG / 128, NN / 128), 256, GEMM_SMEM>>>(b, out, t);
    }
}

// round 5
// speedup vs baseline: 1.0767x; 1.0767x over previous
#include <cuda_runtime.h>
#include <cuda_bf16.h>
#include <cstdint>

#define NN 512
#define TT 32
#define DD 1024
#define HH 1024
#define GG 4096   // 4*H
#define KK 3072   // H + H + D

// ---------------- scratch (device globals; no allocation allowed) -------------
__device__ float g_h[NN * HH];
__device__ float g_c[NN * HH];
__device__ float g_v[(size_t)NN * GG];
__device__ float g_vx[(size_t)NN * TT * GG];          // precomputed x@Wx + b (268 MB)
__device__ __align__(256) __nv_bfloat16 g_hhi[NN * HH], g_hlo[NN * HH];
__device__ __align__(256) __nv_bfloat16 g_ahi[NN * HH], g_alo[NN * HH];
__device__ __align__(256) __nv_bfloat16 g_xhi[(size_t)NN * TT * DD], g_xlo[(size_t)NN * TT * DD];
__device__ __align__(256) __nv_bfloat16 g_wthi[(size_t)GG * KK], g_wtlo[(size_t)GG * KK]; // W^T [4096][3072]

// ---------------- small helpers ------------------------------------------------
__device__ __forceinline__ uint32_t smem_u32(const void* p) {
    uint32_t a;
    asm("{ .reg .u64 t; cvta.to.shared.u64 t, %1; cvt.u32.u64 %0, t; }" : "=r"(a) : "l"(p));
    return a;
}
__device__ __forceinline__ void cp16(uint32_t dst, const void* src) {
    asm volatile("cp.async.cg.shared.global [%0], [%1], 16;" :: "r"(dst), "l"(src));
}
__device__ __forceinline__ void cp_commit() { asm volatile("cp.async.commit_group;" ::: "memory"); }
template <int N> __device__ __forceinline__ void cp_wait() {
    asm volatile("cp.async.wait_group %0;" :: "n"(N) : "memory");
}
__device__ __forceinline__ void split_bf16(float w, __nv_bfloat16& hi, __nv_bfloat16& lo) {
    hi = __float2bfloat16(w);
    lo = __float2bfloat16(w - __bfloat162float(hi));
}
__device__ __forceinline__ void ldsm4(uint32_t& r0, uint32_t& r1, uint32_t& r2, uint32_t& r3,
                                      uint32_t addr) {
    asm volatile("ldmatrix.sync.aligned.m8n8.x4.shared.b16 {%0,%1,%2,%3}, [%4];"
                 : "=r"(r0), "=r"(r1), "=r"(r2), "=r"(r3) : "r"(addr));
}
__device__ __forceinline__ void mma16816(float* d, const uint32_t* a, uint32_t b0, uint32_t b1) {
    asm volatile(
        "mma.sync.aligned.m16n8k16.row.col.f32.bf16.bf16.f32 "
        "{%0,%1,%2,%3}, {%4,%5,%6,%7}, {%8,%9}, {%0,%1,%2,%3};"
        : "+f"(d[0]), "+f"(d[1]), "+f"(d[2]), "+f"(d[3])
        : "r"(a[0]), "r"(a[1]), "r"(a[2]), "r"(a[3]), "r"(b0), "r"(b1));
}

// ---------------- one-time prep kernels ----------------------------------------
// Transpose + hi/lo split of [Wh; Wattn; Wx] (3072 x 4096) -> W^T (4096 x 3072) bf16
__global__ void prep_w(const float* __restrict__ Wx, const float* __restrict__ Wh,
                       const float* __restrict__ Wattn) {
    __shared__ float tile[32][33];
    int k0 = blockIdx.x * 32, n0 = blockIdx.y * 32;
#pragma unroll
    for (int dy = 0; dy < 32; dy += 8) {
        int k = k0 + threadIdx.y + dy;
        int n = n0 + threadIdx.x;
        const float* W;
        int kk = k;
        if (k < 1024)       { W = Wh; }
        else if (k < 2048)  { W = Wattn; kk = k - 1024; }
        else                { W = Wx;    kk = k - 2048; }
        tile[threadIdx.y + dy][threadIdx.x] = W[(size_t)kk * GG + n];
    }
    __syncthreads();
#pragma unroll
    for (int dy = 0; dy < 32; dy += 8) {
        int n = n0 + threadIdx.y + dy;
        int k = k0 + threadIdx.x;
        float w = tile[threadIdx.x][threadIdx.y + dy];
        __nv_bfloat16 hi, lo;
        split_bf16(w, hi, lo);
        g_wthi[(size_t)n * KK + k] = hi;
        g_wtlo[(size_t)n * KK + k] = lo;
    }
}

__global__ void prep_x(const float* __restrict__ x) {
    size_t i = (size_t)blockIdx.x * 256 + threadIdx.x;
    __nv_bfloat16 hi, lo;
    split_bf16(x[i], hi, lo);
    g_xhi[i] = hi;
    g_xlo[i] = lo;
}

// ---------------- init: h0 = c0 = mean over the 16 spatial cells ---------------
__global__ void init_kernel(const float* __restrict__ A) {
    int idx = blockIdx.x * 256 + threadIdx.x;
    const float4* a4 = (const float4*)(A + (size_t)idx * 16);
    float4 a0 = a4[0], a1 = a4[1], a2 = a4[2], a3 = a4[3];
    float s = ((a0.x + a0.y) + (a0.z + a0.w)) + ((a1.x + a1.y) + (a1.z + a1.w))
            + ((a2.x + a2.y) + (a2.z + a2.w)) + ((a3.x + a3.y) + (a3.z + a3.w));
    s *= (1.0f / 16.0f);
    g_h[idx] = s;
    g_c[idx] = s;
    __nv_bfloat16 hi, lo;
    split_bf16(s, hi, lo);
    g_hhi[idx] = hi;
    g_hlo[idx] = lo;
}

// ---------------- attention over 16 spatial cells ------------------------------
__global__ void attn_kernel(const float* __restrict__ A) {
    int n = blockIdx.x;
    const float* Af = A + (size_t)n * HH * 16;
    const float* hp = g_h + (size_t)n * HH;

    float part[16];
#pragma unroll
    for (int k = 0; k < 16; ++k) part[k] = 0.0f;

    for (int j = threadIdx.x; j < HH; j += 256) {
        float hv = hp[j];
        const float4* a4 = (const float4*)(Af + (size_t)j * 16);
        float4 a;
        a = a4[0]; part[0]  += hv * a.x; part[1]  += hv * a.y; part[2]  += hv * a.z; part[3]  += hv * a.w;
        a = a4[1]; part[4]  += hv * a.x; part[5]  += hv * a.y; part[6]  += hv * a.z; part[7]  += hv * a.w;
        a = a4[2]; part[8]  += hv * a.x; part[9]  += hv * a.y; part[10] += hv * a.z; part[11] += hv * a.w;
        a = a4[3]; part[12] += hv * a.x; part[13] += hv * a.y; part[14] += hv * a.z; part[15] += hv * a.w;
    }
#pragma unroll
    for (int k = 0; k < 16; ++k)
#pragma unroll
        for (int off = 16; off; off >>= 1)
            part[k] += __shfl_xor_sync(0xffffffffu, part[k], off);

    __shared__ float sred[8][16];
    __shared__ float sM[16];
    int warp = threadIdx.x >> 5, lane = threadIdx.x & 31;
    if (lane == 0) {
#pragma unroll
        for (int k = 0; k < 16; ++k) sred[warp][k] = part[k];
    }
    __syncthreads();

    if (threadIdx.x < 32) {
        int k = lane & 15;
        float s = 0.0f;
#pragma unroll
        for (int w = 0; w < 8; ++w) s += sred[w][k];
        s *= (1.0f / 32.0f);
        float m = s;
#pragma unroll
        for (int off = 8; off; off >>= 1) m = fmaxf(m, __shfl_xor_sync(0xffffffffu, m, off));
        float e = expf(s - m);
        float sum = e;
#pragma unroll
        for (int off = 8; off; off >>= 1) sum += __shfl_xor_sync(0xffffffffu, sum, off);
        if (lane < 16) sM[lane] = e / sum;
    }
    __syncthreads();

    for (int j = threadIdx.x; j < HH; j += 256) {
        const float4* a4 = (const float4*)(Af + (size_t)j * 16);
        float s = 0.0f;
        float4 a;
        a = a4[0]; s += a.x * sM[0]  + a.y * sM[1]  + a.z * sM[2]  + a.w * sM[3];
        a = a4[1]; s += a.x * sM[4]  + a.y * sM[5]  + a.z * sM[6]  + a.w * sM[7];
        a = a4[2]; s += a.x * sM[8]  + a.y * sM[9]  + a.z * sM[10] + a.w * sM[11];
        a = a4[3]; s += a.x * sM[12] + a.y * sM[13] + a.z * sM[14] + a.w * sM[15];
        size_t idx = (size_t)n * HH + j;
        __nv_bfloat16 hi, lo;
        split_bf16(s, hi, lo);
        g_ahi[idx] = hi;
        g_alo[idx] = lo;
    }
}

// ---------------- shared GEMM machinery (bf16x3 split HMMA) ---------------------
#define STAGE_BYTES 65536
#define A_HI_OFF 0
#define A_LO_OFF 16384
#define B_HI_OFF 32768
#define B_LO_OFF 49152
#define GEMM_SMEM (3 * STAGE_BYTES)

struct WarpCtx {
    uint32_t swb, aRow, aHalf, bRow, bHalf;
};
__device__ __forceinline__ WarpCtx warp_ctx(int wm, int wn, int lane) {
    WarpCtx c;
    c.swb   = (lane & 7) << 4;
    c.aRow  = (uint32_t)(wm * 32 + (lane & 15)) * 128;
    c.aHalf = (uint32_t)(lane >> 4);
    c.bRow  = (uint32_t)(wn * 64 + (lane & 7) + ((lane >> 4) << 3)) * 128;
    c.bHalf = (uint32_t)((lane >> 3) & 1);
    return c;
}

__device__ __forceinline__ void mma_stage(float acc[2][8][4], uint32_t base, const WarpCtx& c) {
    uint32_t ah_base = base + A_HI_OFF, al_base = base + A_LO_OFF;
    uint32_t bh_base = base + B_HI_OFF, bl_base = base + B_LO_OFF;
#pragma unroll
    for (int q = 0; q < 4; ++q) {
        uint32_t aChunk = ((2 * q + c.aHalf) << 4) ^ c.swb;
        uint32_t bChunk = ((2 * q + c.bHalf) << 4) ^ c.swb;
        uint32_t ahf[2][4], alf[2][4];
#pragma unroll
        for (int i = 0; i < 2; ++i) {
            uint32_t ao = c.aRow + (uint32_t)i * 2048 + aChunk;
            ldsm4(ahf[i][0], ahf[i][1], ahf[i][2], ahf[i][3], ah_base + ao);
            ldsm4(alf[i][0], alf[i][1], alf[i][2], alf[i][3], al_base + ao);
        }
        uint32_t bhf[4][4], blf[4][4];
#pragma unroll
        for (int p = 0; p < 4; ++p) {
            uint32_t bo = c.bRow + (uint32_t)p * 2048 + bChunk;
            ldsm4(bhf[p][0], bhf[p][1], bhf[p][2], bhf[p][3], bh_base + bo);
            ldsm4(blf[p][0], blf[p][1], blf[p][2], blf[p][3], bl_base + bo);
        }
#pragma unroll
        for (int i = 0; i < 2; ++i)
#pragma unroll
            for (int g = 0; g < 8; ++g) {
                uint32_t b0h = bhf[g >> 1][(g & 1) * 2], b1h = bhf[g >> 1][(g & 1) * 2 + 1];
                uint32_t b0l = blf[g >> 1][(g & 1) * 2], b1l = blf[g >> 1][(g & 1) * 2 + 1];
                mma16816(acc[i][g], ahf[i], b0h, b1h);   // hi*hi
                mma16816(acc[i][g], ahf[i], b0l, b1l);   // hi*lo
                mma16816(acc[i][g], alf[i], b0h, b1h);   // lo*hi
            }
    }
}

// ---------------- per-step GEMM: v = [h | attn] @ [Wh; Wattn]^T  (K=2048) -------
#define NKT_S 32
__global__ __launch_bounds__(256, 1) void gemm_step(int t) {
    extern __shared__ char dynsmem[];
    uint32_t sb = smem_u32(dynsmem);
    const int tid = threadIdx.x;
    const int wid = tid >> 5, lane = tid & 31;
    const WarpCtx wc = warp_ctx(wid & 3, wid >> 2, lane);
    const int m0 = blockIdx.y * 128;
    const int n0 = blockIdx.x * 128;

    float acc[2][8][4];
#pragma unroll
    for (int i = 0; i < 2; ++i)
#pragma unroll
        for (int g = 0; g < 8; ++g)
#pragma unroll
            for (int r = 0; r < 4; ++r) acc[i][g][r] = 0.0f;

    auto load_tile = [&](int kt, int stage) {
        uint32_t base = sb + stage * STAGE_BYTES;
        const __nv_bfloat16* ahi = (kt < 16) ? g_hhi : g_ahi;
        const __nv_bfloat16* alo = (kt < 16) ? g_hlo : g_alo;
        size_t akoff = (size_t)(kt & 15) * 64;
        size_t bkoff = (size_t)kt * 64;
#pragma unroll
        for (int i = 0; i < 4; ++i) {
            int cidx = tid + i * 256;
            int row = cidx >> 3, c16 = cidx & 7;
            uint32_t off = row * 128 + c16 * 16;
            uint32_t sw = off ^ ((off >> 3) & 0x70);
            size_t aoff = (size_t)(m0 + row) * HH + akoff + (size_t)c16 * 8;
            size_t boff = (size_t)(n0 + row) * KK + bkoff + (size_t)c16 * 8;
            cp16(base + A_HI_OFF + sw, ahi + aoff);
            cp16(base + A_LO_OFF + sw, alo + aoff);
            cp16(base + B_HI_OFF + sw, g_wthi + boff);
            cp16(base + B_LO_OFF + sw, g_wtlo + boff);
        }
    };

    load_tile(0, 0); cp_commit();
    load_tile(1, 1); cp_commit();

    for (int kt = 0; kt < NKT_S; ++kt) {
        cp_wait<1>();
        __syncthreads();
        mma_stage(acc, sb + (kt % 3) * STAGE_BYTES, wc);
        __syncthreads();
        if (kt + 2 < NKT_S) load_tile(kt + 2, (kt + 2) % 3);
        cp_commit();
    }

#pragma unroll
    for (int i = 0; i < 2; ++i) {
        int row0 = m0 + (wid & 3) * 32 + i * 16 + (lane >> 2);
#pragma unroll
        for (int g = 0; g < 8; ++g) {
            int col = n0 + (wid >> 2) * 64 + g * 8 + (lane & 3) * 2;
            *(float2*)&g_v[(size_t)row0 * GG + col]       = make_float2(acc[i][g][0], acc[i][g][1]);
            *(float2*)&g_v[(size_t)(row0 + 8) * GG + col] = make_float2(acc[i][g][2], acc[i][g][3]);
        }
    }
}

// ---------------- one-time GEMM: vx = X @ Wx^T + b  (M=16384, K=1024) -----------
#define NKT_X 16
__global__ __launch_bounds__(256, 1) void gemm_x(const float* __restrict__ b) {
    extern __shared__ char dynsmem[];
    uint32_t sb = smem_u32(dynsmem);
    const int tid = threadIdx.x;
    const int wid = tid >> 5, lane = tid & 31;
    const WarpCtx wc = warp_ctx(wid & 3, wid >> 2, lane);
    const int m0 = blockIdx.y * 128;
    const int n0 = blockIdx.x * 128;

    float acc[2][8][4];
#pragma unroll
    for (int i = 0; i < 2; ++i)
#pragma unroll
        for (int g = 0; g < 8; ++g)
#pragma unroll
            for (int r = 0; r < 4; ++r) acc[i][g][r] = 0.0f;

    auto load_tile = [&](int kt, int stage) {
        uint32_t base = sb + stage * STAGE_BYTES;
        size_t akoff = (size_t)kt * 64;
        size_t bkoff = 2048 + (size_t)kt * 64;
#pragma unroll
        for (int i = 0; i < 4; ++i) {
            int cidx = tid + i * 256;
            int row = cidx >> 3, c16 = cidx & 7;
            uint32_t off = row * 128 + c16 * 16;
            uint32_t sw = off ^ ((off >> 3) & 0x70);
            size_t aoff = (size_t)(m0 + row) * DD + akoff + (size_t)c16 * 8;
            size_t boff = (size_t)(n0 + row) * KK + bkoff + (size_t)c16 * 8;
            cp16(base + A_HI_OFF + sw, g_xhi + aoff);
            cp16(base + A_LO_OFF + sw, g_xlo + aoff);
            cp16(base + B_HI_OFF + sw, g_wthi + boff);
            cp16(base + B_LO_OFF + sw, g_wtlo + boff);
        }
    };

    load_tile(0, 0); cp_commit();
    load_tile(1, 1); cp_commit();

    for (int kt = 0; kt < NKT_X; ++kt) {
        cp_wait<1>();
        __syncthreads();
        mma_stage(acc, sb + (kt % 3) * STAGE_BYTES, wc);
        __syncthreads();
        if (kt + 2 < NKT_X) load_tile(kt + 2, (kt + 2) % 3);
        cp_commit();
    }

#pragma unroll
    for (int i = 0; i < 2; ++i) {
        int row0 = m0 + (wid & 3) * 32 + i * 16 + (lane >> 2);
#pragma unroll
        for (int g = 0; g < 8; ++g) {
            int col = n0 + (wid >> 2) * 64 + g * 8 + (lane & 3) * 2;
            float2 bb = *(const float2*)&b[col];
            *(float2*)&g_vx[(size_t)row0 * GG + col] =
                make_float2(acc[i][g][0] + bb.x, acc[i][g][1] + bb.y);
            *(float2*)&g_vx[(size_t)(row0 + 8) * GG + col] =
                make_float2(acc[i][g][2] + bb.x, acc[i][g][3] + bb.y);
        }
    }
}

// ---------------- gates + state update + output write --------------------------
__global__ void gate_kernel(float* __restrict__ out, int t) {
    int idx = blockIdx.x * 256 + threadIdx.x;
    int n = idx >> 10;
    int j = idx & 1023;
    const float* vr  = g_v  + (size_t)n * GG;
    const float* vxr = g_vx + ((size_t)n * TT + t) * GG;
    float vi = vr[j]        + vxr[j];
    float vf = vr[j + 1024] + vxr[j + 1024];
    float vo = vr[j + 2048] + vxr[j + 2048];
    float vg = vr[j + 3072] + vxr[j + 3072];
    float ig = 1.0f / (1.0f + expf(-vi));
    float fg = 1.0f / (1.0f + expf(-vf));
    float og = 1.0f / (1.0f + expf(-vo));
    float gg = tanhf(vg);
    float c = fg * g_c[idx] + ig * gg;
    float h = og * tanhf(c);
    g_c[idx] = c;
    g_h[idx] = h;
    __nv_bfloat16 hi, lo;
    split_bf16(h, hi, lo);
    g_hhi[idx] = hi;
    g_hlo[idx] = lo;
    out[(size_t)n * (TT * HH) + (size_t)t * HH + j] = h;
}

// ---------------- launch ---------------------------------------------------------
extern "C" void kernel_launch(void* const* d_in, const int* in_sizes, int n_in,
                              void* d_out, int out_size) {
    const float* x     = (const float*)d_in[0];   // (N, T, D)
    const float* A     = (const float*)d_in[1];   // (N, H, 4, 4)
    const float* Wx    = (const float*)d_in[2];   // (D, 4H)
    const float* Wh    = (const float*)d_in[3];   // (H, 4H)
    const float* Wattn = (const float*)d_in[4];   // (H, 4H)
    const float* b     = (const float*)d_in[5];   // (4H,)
    float* out = (float*)d_out;                   // (N, T, H)

    cudaFuncSetAttribute(gemm_step, cudaFuncAttributeMaxDynamicSharedMemorySize, GEMM_SMEM);
    cudaFuncSetAttribute(gemm_x,    cudaFuncAttributeMaxDynamicSharedMemorySize, GEMM_SMEM);

    prep_w<<<dim3(KK / 32, GG / 32), dim3(32, 8)>>>(Wx, Wh, Wattn);
    prep_x<<<(NN * TT * DD) / 256, 256>>>(x);
    init_kernel<<<(NN * HH) / 256, 256>>>(A);
    gemm_x<<<dim3(GG / 128, (NN * TT) / 128), 256, GEMM_SMEM>>>(b);
    for (int t = 0; t < TT; ++t) {
        attn_kernel<<<NN, 256>>>(A);
        gemm_step<<<dim3(GG / 128, NN / 128), 256, GEMM_SMEM>>>(t);
        gate_kernel<<<(NN * HH) / 256, 256>>>(out, t);
    }
}

// round 7
// speedup vs baseline: 1.5392x; 1.4296x over previous
#include <cuda_runtime.h>
#include <cuda_fp16.h>
#include <cstdint>

#define NN 512
#define TT 32
#define DD 1024
#define HH 1024
#define GG 4096   // 4*H
#define KK 3072   // H + H + D

// ---------------- scratch (device globals; no allocation allowed) -------------
__device__ float g_c[NN * HH];
__device__ float g_v[(size_t)NN * GG];
__device__ float g_vx[(size_t)NN * TT * GG];          // precomputed x@Wx + b
__device__ __align__(256) __half g_hh[NN * HH];       // h (fp16)
__device__ __align__(256) __half g_ah[NN * HH];       // attn (fp16)
__device__ __align__(256) __half g_xh[(size_t)NN * TT * DD];   // x (fp16)
__device__ __align__(256) __half g_Ah[(size_t)NN * HH * 16];   // A (fp16)
__device__ __align__(256) __half g_wthi[(size_t)GG * KK], g_wtlo[(size_t)GG * KK]; // W^T hi/lo

// ---------------- small helpers ------------------------------------------------
__device__ __forceinline__ uint32_t smem_u32(const void* p) {
    uint32_t a;
    asm("{ .reg .u64 t; cvta.to.shared.u64 t, %1; cvt.u32.u64 %0, t; }" : "=r"(a) : "l"(p));
    return a;
}
__device__ __forceinline__ void cp16(uint32_t dst, const void* src) {
    asm volatile("cp.async.cg.shared.global [%0], [%1], 16;" :: "r"(dst), "l"(src));
}
__device__ __forceinline__ void cp_commit() { asm volatile("cp.async.commit_group;" ::: "memory"); }
template <int N> __device__ __forceinline__ void cp_wait() {
    asm volatile("cp.async.wait_group %0;" :: "n"(N) : "memory");
}
__device__ __forceinline__ void split_h16(float w, __half& hi, __half& lo) {
    hi = __float2half(w);
    lo = __float2half(w - __half2float(hi));
}
__device__ __forceinline__ void ldsm4(uint32_t& r0, uint32_t& r1, uint32_t& r2, uint32_t& r3,
                                      uint32_t addr) {
    asm volatile("ldmatrix.sync.aligned.m8n8.x4.shared.b16 {%0,%1,%2,%3}, [%4];"
                 : "=r"(r0), "=r"(r1), "=r"(r2), "=r"(r3) : "r"(addr));
}
__device__ __forceinline__ void mma16816(float* d, const uint32_t* a, uint32_t b0, uint32_t b1) {
    asm volatile(
        "mma.sync.aligned.m16n8k16.row.col.f32.f16.f16.f32 "
        "{%0,%1,%2,%3}, {%4,%5,%6,%7}, {%8,%9}, {%0,%1,%2,%3};"
        : "+f"(d[0]), "+f"(d[1]), "+f"(d[2]), "+f"(d[3])
        : "r"(a[0]), "r"(a[1]), "r"(a[2]), "r"(a[3]), "r"(b0), "r"(b1));
}

// ---------------- one-time prep kernels ----------------------------------------
// Transpose + fp16 hi/lo split of [Wh; Wattn; Wx] (3072 x 4096) -> W^T (4096 x 3072)
__global__ void prep_w(const float* __restrict__ Wx, const float* __restrict__ Wh,
                       const float* __restrict__ Wattn) {
    __shared__ float tile[32][33];
    int k0 = blockIdx.x * 32, n0 = blockIdx.y * 32;
#pragma unroll
    for (int dy = 0; dy < 32; dy += 8) {
        int k = k0 + threadIdx.y + dy;
        int n = n0 + threadIdx.x;
        const float* W;
        int kk = k;
        if (k < 1024)       { W = Wh; }
        else if (k < 2048)  { W = Wattn; kk = k - 1024; }
        else                { W = Wx;    kk = k - 2048; }
        tile[threadIdx.y + dy][threadIdx.x] = W[(size_t)kk * GG + n];
    }
    __syncthreads();
#pragma unroll
    for (int dy = 0; dy < 32; dy += 8) {
        int n = n0 + threadIdx.y + dy;
        int k = k0 + threadIdx.x;
        float w = tile[threadIdx.x][threadIdx.y + dy];
        __half hi, lo;
        split_h16(w, hi, lo);
        g_wthi[(size_t)n * KK + k] = hi;
        g_wtlo[(size_t)n * KK + k] = lo;
    }
}

// fp32 -> fp16 conversions; destinations are device globals referenced IN DEVICE CODE
__global__ void cvt_x(const float* __restrict__ src) {
    size_t i = (size_t)blockIdx.x * 256 + threadIdx.x;
    float4 f = ((const float4*)src)[i];
    union { uint2 u; __half2 h[2]; } U;
    U.h[0] = __floats2half2_rn(f.x, f.y);
    U.h[1] = __floats2half2_rn(f.z, f.w);
    ((uint2*)g_xh)[i] = U.u;
}
__global__ void cvt_A(const float* __restrict__ src) {
    size_t i = (size_t)blockIdx.x * 256 + threadIdx.x;
    float4 f = ((const float4*)src)[i];
    union { uint2 u; __half2 h[2]; } U;
    U.h[0] = __floats2half2_rn(f.x, f.y);
    U.h[1] = __floats2half2_rn(f.z, f.w);
    ((uint2*)g_Ah)[i] = U.u;
}

// ---------------- init: h0 = c0 = mean over the 16 spatial cells ---------------
__global__ void init_kernel(const float* __restrict__ A) {
    int idx = blockIdx.x * 256 + threadIdx.x;
    const float4* a4 = (const float4*)(A + (size_t)idx * 16);
    float4 a0 = a4[0], a1 = a4[1], a2 = a4[2], a3 = a4[3];
    float s = ((a0.x + a0.y) + (a0.z + a0.w)) + ((a1.x + a1.y) + (a1.z + a1.w))
            + ((a2.x + a2.y) + (a2.z + a2.w)) + ((a3.x + a3.y) + (a3.z + a3.w));
    s *= (1.0f / 16.0f);
    g_c[idx] = s;
    g_hh[idx] = __float2half(s);
}

// ---------------- attention over 16 spatial cells (fp16 A, fp16 h) -------------
__global__ void attn_kernel() {
    int n = blockIdx.x;
    const __half* Af = g_Ah + (size_t)n * HH * 16;
    const __half* hp = g_hh + (size_t)n * HH;

    float part[16];
#pragma unroll
    for (int k = 0; k < 16; ++k) part[k] = 0.0f;

    for (int j = threadIdx.x; j < HH; j += 256) {
        float hv = __half2float(hp[j]);
        union { uint4 u; __half2 h[4]; } U0, U1;
        U0.u = *(const uint4*)(Af + (size_t)j * 16);
        U1.u = *(const uint4*)(Af + (size_t)j * 16 + 8);
#pragma unroll
        for (int q = 0; q < 4; ++q) {
            float2 f0 = __half22float2(U0.h[q]);
            float2 f1 = __half22float2(U1.h[q]);
            part[2 * q]     += hv * f0.x;
            part[2 * q + 1] += hv * f0.y;
            part[8 + 2 * q]     += hv * f1.x;
            part[8 + 2 * q + 1] += hv * f1.y;
        }
    }
#pragma unroll
    for (int k = 0; k < 16; ++k)
#pragma unroll
        for (int off = 16; off; off >>= 1)
            part[k] += __shfl_xor_sync(0xffffffffu, part[k], off);

    __shared__ float sred[8][16];
    __shared__ float sM[16];
    int warp = threadIdx.x >> 5, lane = threadIdx.x & 31;
    if (lane == 0) {
#pragma unroll
        for (int k = 0; k < 16; ++k) sred[warp][k] = part[k];
    }
    __syncthreads();

    if (threadIdx.x < 32) {
        int k = lane & 15;
        float s = 0.0f;
#pragma unroll
        for (int w = 0; w < 8; ++w) s += sred[w][k];
        s *= (1.0f / 32.0f);                         // / sqrt(H)
        float m = s;
#pragma unroll
        for (int off = 8; off; off >>= 1) m = fmaxf(m, __shfl_xor_sync(0xffffffffu, m, off));
        float e = expf(s - m);
        float sum = e;
#pragma unroll
        for (int off = 8; off; off >>= 1) sum += __shfl_xor_sync(0xffffffffu, sum, off);
        if (lane < 16) sM[lane] = e / sum;
    }
    __syncthreads();

    for (int j = threadIdx.x; j < HH; j += 256) {
        union { uint4 u; __half2 h[4]; } U0, U1;
        U0.u = *(const uint4*)(Af + (size_t)j * 16);
        U1.u = *(const uint4*)(Af + (size_t)j * 16 + 8);
        float s = 0.0f;
#pragma unroll
        for (int q = 0; q < 4; ++q) {
            float2 f0 = __half22float2(U0.h[q]);
            float2 f1 = __half22float2(U1.h[q]);
            s += f0.x * sM[2 * q] + f0.y * sM[2 * q + 1];
            s += f1.x * sM[8 + 2 * q] + f1.y * sM[8 + 2 * q + 1];
        }
        g_ah[(size_t)n * HH + j] = __float2half(s);
    }
}

// ---------------- shared GEMM machinery (fp16 2-pass HMMA) ----------------------
#define STAGE_BYTES 49152
#define A_OFF 0
#define B_HI_OFF 16384
#define B_LO_OFF 32768
#define GEMM_SMEM (3 * STAGE_BYTES)

struct WarpCtx {
    uint32_t swb, aRow, aHalf, bRow, bHalf;
};
__device__ __forceinline__ WarpCtx warp_ctx(int wm, int wn, int lane) {
    WarpCtx c;
    c.swb   = (lane & 7) << 4;
    c.aRow  = (uint32_t)(wm * 32 + (lane & 15)) * 128;
    c.aHalf = (uint32_t)(lane >> 4);
    c.bRow  = (uint32_t)(wn * 64 + (lane & 7) + ((lane >> 4) << 3)) * 128;
    c.bHalf = (uint32_t)((lane >> 3) & 1);
    return c;
}

__device__ __forceinline__ void mma_stage(float acc[2][8][4], uint32_t base, const WarpCtx& c) {
    uint32_t a_base = base + A_OFF, bh_base = base + B_HI_OFF, bl_base = base + B_LO_OFF;
#pragma unroll
    for (int q = 0; q < 4; ++q) {
        uint32_t aChunk = ((2 * q + c.aHalf) << 4) ^ c.swb;
        uint32_t bChunk = ((2 * q + c.bHalf) << 4) ^ c.swb;
        uint32_t af[2][4];
#pragma unroll
        for (int i = 0; i < 2; ++i) {
            uint32_t ao = c.aRow + (uint32_t)i * 2048 + aChunk;
            ldsm4(af[i][0], af[i][1], af[i][2], af[i][3], a_base + ao);
        }
        uint32_t bhf[4][4], blf[4][4];
#pragma unroll
        for (int p = 0; p < 4; ++p) {
            uint32_t bo = c.bRow + (uint32_t)p * 2048 + bChunk;
            ldsm4(bhf[p][0], bhf[p][1], bhf[p][2], bhf[p][3], bh_base + bo);
            ldsm4(blf[p][0], blf[p][1], blf[p][2], blf[p][3], bl_base + bo);
        }
#pragma unroll
        for (int i = 0; i < 2; ++i)
#pragma unroll
            for (int g = 0; g < 8; ++g) {
                uint32_t b0h = bhf[g >> 1][(g & 1) * 2], b1h = bhf[g >> 1][(g & 1) * 2 + 1];
                uint32_t b0l = blf[g >> 1][(g & 1) * 2], b1l = blf[g >> 1][(g & 1) * 2 + 1];
                mma16816(acc[i][g], af[i], b0h, b1h);   // a * w_hi
                mma16816(acc[i][g], af[i], b0l, b1l);   // a * w_lo
            }
    }
}

// ---------------- per-step GEMM: v = [h | attn] @ [Wh; Wattn]^T  (K=2048) -------
#define NKT_S 32
__global__ __launch_bounds__(256, 1) void gemm_step() {
    extern __shared__ char dynsmem[];
    uint32_t sb = smem_u32(dynsmem);
    const int tid = threadIdx.x;
    const int wid = tid >> 5, lane = tid & 31;
    const WarpCtx wc = warp_ctx(wid & 3, wid >> 2, lane);
    const int m0 = blockIdx.y * 128;
    const int n0 = blockIdx.x * 128;

    float acc[2][8][4];
#pragma unroll
    for (int i = 0; i < 2; ++i)
#pragma unroll
        for (int g = 0; g < 8; ++g)
#pragma unroll
            for (int r = 0; r < 4; ++r) acc[i][g][r] = 0.0f;

    auto load_tile = [&](int kt, int stage) {
        uint32_t base = sb + stage * STAGE_BYTES;
        const __half* ap = (kt < 16) ? g_hh : g_ah;
        size_t akoff = (size_t)(kt & 15) * 64;
        size_t bkoff = (size_t)kt * 64;
#pragma unroll
        for (int i = 0; i < 4; ++i) {
            int cidx = tid + i * 256;
            int row = cidx >> 3, c16 = cidx & 7;
            uint32_t off = row * 128 + c16 * 16;
            uint32_t sw = off ^ ((off >> 3) & 0x70);
            size_t aoff = (size_t)(m0 + row) * HH + akoff + (size_t)c16 * 8;
            size_t boff = (size_t)(n0 + row) * KK + bkoff + (size_t)c16 * 8;
            cp16(base + A_OFF + sw, ap + aoff);
            cp16(base + B_HI_OFF + sw, g_wthi + boff);
            cp16(base + B_LO_OFF + sw, g_wtlo + boff);
        }
    };

    load_tile(0, 0); cp_commit();
    load_tile(1, 1); cp_commit();

    for (int kt = 0; kt < NKT_S; ++kt) {
        cp_wait<1>();
        __syncthreads();
        mma_stage(acc, sb + (kt % 3) * STAGE_BYTES, wc);
        __syncthreads();
        if (kt + 2 < NKT_S) load_tile(kt + 2, (kt + 2) % 3);
        cp_commit();
    }

#pragma unroll
    for (int i = 0; i < 2; ++i) {
        int row0 = m0 + (wid & 3) * 32 + i * 16 + (lane >> 2);
#pragma unroll
        for (int g = 0; g < 8; ++g) {
            int col = n0 + (wid >> 2) * 64 + g * 8 + (lane & 3) * 2;
            *(float2*)&g_v[(size_t)row0 * GG + col]       = make_float2(acc[i][g][0], acc[i][g][1]);
            *(float2*)&g_v[(size_t)(row0 + 8) * GG + col] = make_float2(acc[i][g][2], acc[i][g][3]);
        }
    }
}

// ---------------- one-time GEMM: vx = X @ Wx^T + b  (M=16384, K=1024) -----------
#define NKT_X 16
__global__ __launch_bounds__(256, 1) void gemm_x(const float* __restrict__ b) {
    extern __shared__ char dynsmem[];
    uint32_t sb = smem_u32(dynsmem);
    const int tid = threadIdx.x;
    const int wid = tid >> 5, lane = tid & 31;
    const WarpCtx wc = warp_ctx(wid & 3, wid >> 2, lane);
    const int m0 = blockIdx.y * 128;
    const int n0 = blockIdx.x * 128;

    float acc[2][8][4];
#pragma unroll
    for (int i = 0; i < 2; ++i)
#pragma unroll
        for (int g = 0; g < 8; ++g)
#pragma unroll
            for (int r = 0; r < 4; ++r) acc[i][g][r] = 0.0f;

    auto load_tile = [&](int kt, int stage) {
        uint32_t base = sb + stage * STAGE_BYTES;
        size_t akoff = (size_t)kt * 64;
        size_t bkoff = 2048 + (size_t)kt * 64;
#pragma unroll
        for (int i = 0; i < 4; ++i) {
            int cidx = tid + i * 256;
            int row = cidx >> 3, c16 = cidx & 7;
            uint32_t off = row * 128 + c16 * 16;
            uint32_t sw = off ^ ((off >> 3) & 0x70);
            size_t aoff = (size_t)(m0 + row) * DD + akoff + (size_t)c16 * 8;
            size_t boff = (size_t)(n0 + row) * KK + bkoff + (size_t)c16 * 8;
            cp16(base + A_OFF + sw, g_xh + aoff);
            cp16(base + B_HI_OFF + sw, g_wthi + boff);
            cp16(base + B_LO_OFF + sw, g_wtlo + boff);
        }
    };

    load_tile(0, 0); cp_commit();
    load_tile(1, 1); cp_commit();

    for (int kt = 0; kt < NKT_X; ++kt) {
        cp_wait<1>();
        __syncthreads();
        mma_stage(acc, sb + (kt % 3) * STAGE_BYTES, wc);
        __syncthreads();
        if (kt + 2 < NKT_X) load_tile(kt + 2, (kt + 2) % 3);
        cp_commit();
    }

#pragma unroll
    for (int i = 0; i < 2; ++i) {
        int row0 = m0 + (wid & 3) * 32 + i * 16 + (lane >> 2);
#pragma unroll
        for (int g = 0; g < 8; ++g) {
            int col = n0 + (wid >> 2) * 64 + g * 8 + (lane & 3) * 2;
            float2 bb = *(const float2*)&b[col];
            *(float2*)&g_vx[(size_t)row0 * GG + col] =
                make_float2(acc[i][g][0] + bb.x, acc[i][g][1] + bb.y);
            *(float2*)&g_vx[(size_t)(row0 + 8) * GG + col] =
                make_float2(acc[i][g][2] + bb.x, acc[i][g][3] + bb.y);
        }
    }
}

// ---------------- gates + state update + output write --------------------------
__global__ void gate_kernel(float* __restrict__ out, int t) {
    int idx = blockIdx.x * 256 + threadIdx.x;
    int n = idx >> 10;
    int j = idx & 1023;
    const float* vr  = g_v  + (size_t)n * GG;
    const float* vxr = g_vx + ((size_t)n * TT + t) * GG;
    float vi = vr[j]        + vxr[j];
    float vf = vr[j + 1024] + vxr[j + 1024];
    float vo = vr[j + 2048] + vxr[j + 2048];
    float vg = vr[j + 3072] + vxr[j + 3072];
    float ig = 1.0f / (1.0f + expf(-vi));
    float fg = 1.0f / (1.0f + expf(-vf));
    float og = 1.0f / (1.0f + expf(-vo));
    float gg = tanhf(vg);
    float c = fg * g_c[idx] + ig * gg;
    float h = og * tanhf(c);
    g_c[idx] = c;
    g_hh[idx] = __float2half(h);
    out[(size_t)n * (TT * HH) + (size_t)t * HH + j] = h;
}

// ---------------- launch ---------------------------------------------------------
extern "C" void kernel_launch(void* const* d_in, const int* in_sizes, int n_in,
                              void* d_out, int out_size) {
    const float* x     = (const float*)d_in[0];   // (N, T, D)
    const float* A     = (const float*)d_in[1];   // (N, H, 4, 4)
    const float* Wx    = (const float*)d_in[2];   // (D, 4H)
    const float* Wh    = (const float*)d_in[3];   // (H, 4H)
    const float* Wattn = (const float*)d_in[4];   // (H, 4H)
    const float* b     = (const float*)d_in[5];   // (4H,)
    float* out = (float*)d_out;                   // (N, T, H)

    cudaFuncSetAttribute(gemm_step, cudaFuncAttributeMaxDynamicSharedMemorySize, GEMM_SMEM);
    cudaFuncSetAttribute(gemm_x,    cudaFuncAttributeMaxDynamicSharedMemorySize, GEMM_SMEM);

    prep_w<<<dim3(KK / 32, GG / 32), dim3(32, 8)>>>(Wx, Wh, Wattn);
    cvt_x<<<(NN * TT * DD) / 1024, 256>>>(x);
    cvt_A<<<(NN * HH * 16) / 1024, 256>>>(A);
    init_kernel<<<(NN * HH) / 256, 256>>>(A);
    gemm_x<<<dim3(GG / 128, (NN * TT) / 128), 256, GEMM_SMEM>>>(b);
    for (int t = 0; t < TT; ++t) {
        attn_kernel<<<NN, 256>>>();
        gemm_step<<<dim3(GG / 128, NN / 128), 256, GEMM_SMEM>>>();
        gate_kernel<<<(NN * HH) / 256, 256>>>(out, t);
    }
}

// round 8
// speedup vs baseline: 2.2132x; 1.4378x over previous
#include <cuda_runtime.h>
#include <cuda_fp16.h>
#include <cstdint>

#define NN 512
#define TT 32
#define DD 1024
#define HH 1024
#define GG 4096   // 4*H
#define KK 3072   // H + H + D

// ---------------- scratch (device globals; no allocation allowed) -------------
__device__ float g_c[NN * HH];
__device__ float g_v[(size_t)NN * GG];
__device__ float g_vx[(size_t)NN * TT * GG];          // precomputed x@Wx + b
__device__ __align__(256) __half g_hh[NN * HH];       // h (fp16)
__device__ __align__(256) __half g_ah[NN * HH];       // attn (fp16)
__device__ __align__(256) __half g_xh[(size_t)NN * TT * DD];   // x (fp16)
__device__ __align__(256) __half g_Ah[(size_t)NN * HH * 16];   // A (fp16)
__device__ __align__(256) __half g_wt[(size_t)GG * KK];        // W^T fp16 [4096][3072]

// ---------------- small helpers ------------------------------------------------
__device__ __forceinline__ uint32_t smem_u32(const void* p) {
    uint32_t a;
    asm("{ .reg .u64 t; cvta.to.shared.u64 t, %1; cvt.u32.u64 %0, t; }" : "=r"(a) : "l"(p));
    return a;
}
__device__ __forceinline__ void cp16(uint32_t dst, const void* src) {
    asm volatile("cp.async.cg.shared.global [%0], [%1], 16;" :: "r"(dst), "l"(src));
}
__device__ __forceinline__ void cp_commit() { asm volatile("cp.async.commit_group;" ::: "memory"); }
template <int N> __device__ __forceinline__ void cp_wait() {
    asm volatile("cp.async.wait_group %0;" :: "n"(N) : "memory");
}
__device__ __forceinline__ void ldsm4(uint32_t& r0, uint32_t& r1, uint32_t& r2, uint32_t& r3,
                                      uint32_t addr) {
    asm volatile("ldmatrix.sync.aligned.m8n8.x4.shared.b16 {%0,%1,%2,%3}, [%4];"
                 : "=r"(r0), "=r"(r1), "=r"(r2), "=r"(r3) : "r"(addr));
}
__device__ __forceinline__ void mma16816(float* d, const uint32_t* a, uint32_t b0, uint32_t b1) {
    asm volatile(
        "mma.sync.aligned.m16n8k16.row.col.f32.f16.f16.f32 "
        "{%0,%1,%2,%3}, {%4,%5,%6,%7}, {%8,%9}, {%0,%1,%2,%3};"
        : "+f"(d[0]), "+f"(d[1]), "+f"(d[2]), "+f"(d[3])
        : "r"(a[0]), "r"(a[1]), "r"(a[2]), "r"(a[3]), "r"(b0), "r"(b1));
}

// ---------------- one-time prep kernels ----------------------------------------
// Transpose + fp16 round of [Wh; Wattn; Wx] (3072 x 4096) -> W^T (4096 x 3072)
__global__ void prep_w(const float* __restrict__ Wx, const float* __restrict__ Wh,
                       const float* __restrict__ Wattn) {
    __shared__ float tile[32][33];
    int k0 = blockIdx.x * 32, n0 = blockIdx.y * 32;
#pragma unroll
    for (int dy = 0; dy < 32; dy += 8) {
        int k = k0 + threadIdx.y + dy;
        int n = n0 + threadIdx.x;
        const float* W;
        int kk = k;
        if (k < 1024)       { W = Wh; }
        else if (k < 2048)  { W = Wattn; kk = k - 1024; }
        else                { W = Wx;    kk = k - 2048; }
        tile[threadIdx.y + dy][threadIdx.x] = W[(size_t)kk * GG + n];
    }
    __syncthreads();
#pragma unroll
    for (int dy = 0; dy < 32; dy += 8) {
        int n = n0 + threadIdx.y + dy;
        int k = k0 + threadIdx.x;
        g_wt[(size_t)n * KK + k] = __float2half(tile[threadIdx.x][threadIdx.y + dy]);
    }
}

// fp32 -> fp16 conversions; destinations are device globals referenced in device code
__global__ void cvt_x(const float* __restrict__ src) {
    size_t i = (size_t)blockIdx.x * 256 + threadIdx.x;
    float4 f = ((const float4*)src)[i];
    union { uint2 u; __half2 h[2]; } U;
    U.h[0] = __floats2half2_rn(f.x, f.y);
    U.h[1] = __floats2half2_rn(f.z, f.w);
    ((uint2*)g_xh)[i] = U.u;
}
__global__ void cvt_A(const float* __restrict__ src) {
    size_t i = (size_t)blockIdx.x * 256 + threadIdx.x;
    float4 f = ((const float4*)src)[i];
    union { uint2 u; __half2 h[2]; } U;
    U.h[0] = __floats2half2_rn(f.x, f.y);
    U.h[1] = __floats2half2_rn(f.z, f.w);
    ((uint2*)g_Ah)[i] = U.u;
}

// ---------------- init: h0 = c0 = mean over the 16 spatial cells ---------------
__global__ void init_kernel(const float* __restrict__ A) {
    int idx = blockIdx.x * 256 + threadIdx.x;
    const float4* a4 = (const float4*)(A + (size_t)idx * 16);
    float4 a0 = a4[0], a1 = a4[1], a2 = a4[2], a3 = a4[3];
    float s = ((a0.x + a0.y) + (a0.z + a0.w)) + ((a1.x + a1.y) + (a1.z + a1.w))
            + ((a2.x + a2.y) + (a2.z + a2.w)) + ((a3.x + a3.y) + (a3.z + a3.w));
    s *= (1.0f / 16.0f);
    g_c[idx] = s;
    g_hh[idx] = __float2half(s);
}

// ---------------- attention over 16 spatial cells (fp16 A, fp16 h) -------------
__global__ void attn_kernel() {
    int n = blockIdx.x;
    const __half* Af = g_Ah + (size_t)n * HH * 16;
    const __half* hp = g_hh + (size_t)n * HH;

    float part[16];
#pragma unroll
    for (int k = 0; k < 16; ++k) part[k] = 0.0f;

    for (int j = threadIdx.x; j < HH; j += 256) {
        float hv = __half2float(hp[j]);
        union { uint4 u; __half2 h[4]; } U0, U1;
        U0.u = *(const uint4*)(Af + (size_t)j * 16);
        U1.u = *(const uint4*)(Af + (size_t)j * 16 + 8);
#pragma unroll
        for (int q = 0; q < 4; ++q) {
            float2 f0 = __half22float2(U0.h[q]);
            float2 f1 = __half22float2(U1.h[q]);
            part[2 * q]     += hv * f0.x;
            part[2 * q + 1] += hv * f0.y;
            part[8 + 2 * q]     += hv * f1.x;
            part[8 + 2 * q + 1] += hv * f1.y;
        }
    }
#pragma unroll
    for (int k = 0; k < 16; ++k)
#pragma unroll
        for (int off = 16; off; off >>= 1)
            part[k] += __shfl_xor_sync(0xffffffffu, part[k], off);

    __shared__ float sred[8][16];
    __shared__ float sM[16];
    int warp = threadIdx.x >> 5, lane = threadIdx.x & 31;
    if (lane == 0) {
#pragma unroll
        for (int k = 0; k < 16; ++k) sred[warp][k] = part[k];
    }
    __syncthreads();

    if (threadIdx.x < 32) {
        int k = lane & 15;
        float s = 0.0f;
#pragma unroll
        for (int w = 0; w < 8; ++w) s += sred[w][k];
        s *= (1.0f / 32.0f);                         // / sqrt(H)
        float m = s;
#pragma unroll
        for (int off = 8; off; off >>= 1) m = fmaxf(m, __shfl_xor_sync(0xffffffffu, m, off));
        float e = expf(s - m);
        float sum = e;
#pragma unroll
        for (int off = 8; off; off >>= 1) sum += __shfl_xor_sync(0xffffffffu, sum, off);
        if (lane < 16) sM[lane] = e / sum;
    }
    __syncthreads();

    for (int j = threadIdx.x; j < HH; j += 256) {
        union { uint4 u; __half2 h[4]; } U0, U1;
        U0.u = *(const uint4*)(Af + (size_t)j * 16);
        U1.u = *(const uint4*)(Af + (size_t)j * 16 + 8);
        float s = 0.0f;
#pragma unroll
        for (int q = 0; q < 4; ++q) {
            float2 f0 = __half22float2(U0.h[q]);
            float2 f1 = __half22float2(U1.h[q]);
            s += f0.x * sM[2 * q] + f0.y * sM[2 * q + 1];
            s += f1.x * sM[8 + 2 * q] + f1.y * sM[8 + 2 * q + 1];
        }
        g_ah[(size_t)n * HH + j] = __float2half(s);
    }
}

// ---------------- shared GEMM machinery (fp16 single-pass HMMA) -----------------
#define STAGE_BYTES 32768
#define A_OFF 0
#define B_OFF 16384
#define GEMM_SMEM (3 * STAGE_BYTES)

struct WarpCtx {
    uint32_t swb, aRow, aHalf, bRow, bHalf;
};
__device__ __forceinline__ WarpCtx warp_ctx(int wm, int wn, int lane) {
    WarpCtx c;
    c.swb   = (lane & 7) << 4;
    c.aRow  = (uint32_t)(wm * 32 + (lane & 15)) * 128;
    c.aHalf = (uint32_t)(lane >> 4);
    c.bRow  = (uint32_t)(wn * 64 + (lane & 7) + ((lane >> 4) << 3)) * 128;
    c.bHalf = (uint32_t)((lane >> 3) & 1);
    return c;
}

__device__ __forceinline__ void mma_stage(float acc[2][8][4], uint32_t base, const WarpCtx& c) {
    uint32_t a_base = base + A_OFF, b_base = base + B_OFF;
#pragma unroll
    for (int q = 0; q < 4; ++q) {
        uint32_t aChunk = ((2 * q + c.aHalf) << 4) ^ c.swb;
        uint32_t bChunk = ((2 * q + c.bHalf) << 4) ^ c.swb;
        uint32_t af[2][4];
#pragma unroll
        for (int i = 0; i < 2; ++i) {
            uint32_t ao = c.aRow + (uint32_t)i * 2048 + aChunk;
            ldsm4(af[i][0], af[i][1], af[i][2], af[i][3], a_base + ao);
        }
        uint32_t bf[4][4];
#pragma unroll
        for (int p = 0; p < 4; ++p) {
            uint32_t bo = c.bRow + (uint32_t)p * 2048 + bChunk;
            ldsm4(bf[p][0], bf[p][1], bf[p][2], bf[p][3], b_base + bo);
        }
#pragma unroll
        for (int i = 0; i < 2; ++i)
#pragma unroll
            for (int g = 0; g < 8; ++g) {
                mma16816(acc[i][g], af[i],
                         bf[g >> 1][(g & 1) * 2], bf[g >> 1][(g & 1) * 2 + 1]);
            }
    }
}

// ---------------- per-step GEMM: v = [h | attn] @ [Wh; Wattn]^T  (K=2048) -------
#define NKT_S 32
__global__ __launch_bounds__(256, 1) void gemm_step() {
    extern __shared__ char dynsmem[];
    uint32_t sb = smem_u32(dynsmem);
    const int tid = threadIdx.x;
    const int wid = tid >> 5, lane = tid & 31;
    const WarpCtx wc = warp_ctx(wid & 3, wid >> 2, lane);
    const int m0 = blockIdx.y * 128;
    const int n0 = blockIdx.x * 128;

    float acc[2][8][4];
#pragma unroll
    for (int i = 0; i < 2; ++i)
#pragma unroll
        for (int g = 0; g < 8; ++g)
#pragma unroll
            for (int r = 0; r < 4; ++r) acc[i][g][r] = 0.0f;

    auto load_tile = [&](int kt, int stage) {
        uint32_t base = sb + stage * STAGE_BYTES;
        const __half* ap = (kt < 16) ? g_hh : g_ah;
        size_t akoff = (size_t)(kt & 15) * 64;
        size_t bkoff = (size_t)kt * 64;
#pragma unroll
        for (int i = 0; i < 4; ++i) {
            int cidx = tid + i * 256;
            int row = cidx >> 3, c16 = cidx & 7;
            uint32_t off = row * 128 + c16 * 16;
            uint32_t sw = off ^ ((off >> 3) & 0x70);
            size_t aoff = (size_t)(m0 + row) * HH + akoff + (size_t)c16 * 8;
            size_t boff = (size_t)(n0 + row) * KK + bkoff + (size_t)c16 * 8;
            cp16(base + A_OFF + sw, ap + aoff);
            cp16(base + B_OFF + sw, g_wt + boff);
        }
    };

    load_tile(0, 0); cp_commit();
    load_tile(1, 1); cp_commit();

    for (int kt = 0; kt < NKT_S; ++kt) {
        cp_wait<1>();
        __syncthreads();
        mma_stage(acc, sb + (kt % 3) * STAGE_BYTES, wc);
        __syncthreads();
        if (kt + 2 < NKT_S) load_tile(kt + 2, (kt + 2) % 3);
        cp_commit();
    }

#pragma unroll
    for (int i = 0; i < 2; ++i) {
        int row0 = m0 + (wid & 3) * 32 + i * 16 + (lane >> 2);
#pragma unroll
        for (int g = 0; g < 8; ++g) {
            int col = n0 + (wid >> 2) * 64 + g * 8 + (lane & 3) * 2;
            *(float2*)&g_v[(size_t)row0 * GG + col]       = make_float2(acc[i][g][0], acc[i][g][1]);
            *(float2*)&g_v[(size_t)(row0 + 8) * GG + col] = make_float2(acc[i][g][2], acc[i][g][3]);
        }
    }
}

// ---------------- one-time GEMM: vx = X @ Wx^T + b  (M=16384, K=1024) -----------
#define NKT_X 16
__global__ __launch_bounds__(256, 1) void gemm_x(const float* __restrict__ b) {
    extern __shared__ char dynsmem[];
    uint32_t sb = smem_u32(dynsmem);
    const int tid = threadIdx.x;
    const int wid = tid >> 5, lane = tid & 31;
    const WarpCtx wc = warp_ctx(wid & 3, wid >> 2, lane);
    const int m0 = blockIdx.y * 128;
    const int n0 = blockIdx.x * 128;

    float acc[2][8][4];
#pragma unroll
    for (int i = 0; i < 2; ++i)
#pragma unroll
        for (int g = 0; g < 8; ++g)
#pragma unroll
            for (int r = 0; r < 4; ++r) acc[i][g][r] = 0.0f;

    auto load_tile = [&](int kt, int stage) {
        uint32_t base = sb + stage * STAGE_BYTES;
        size_t akoff = (size_t)kt * 64;
        size_t bkoff = 2048 + (size_t)kt * 64;
#pragma unroll
        for (int i = 0; i < 4; ++i) {
            int cidx = tid + i * 256;
            int row = cidx >> 3, c16 = cidx & 7;
            uint32_t off = row * 128 + c16 * 16;
            uint32_t sw = off ^ ((off >> 3) & 0x70);
            size_t aoff = (size_t)(m0 + row) * DD + akoff + (size_t)c16 * 8;
            size_t boff = (size_t)(n0 + row) * KK + bkoff + (size_t)c16 * 8;
            cp16(base + A_OFF + sw, g_xh + aoff);
            cp16(base + B_OFF + sw, g_wt + boff);
        }
    };

    load_tile(0, 0); cp_commit();
    load_tile(1, 1); cp_commit();

    for (int kt = 0; kt < NKT_X; ++kt) {
        cp_wait<1>();
        __syncthreads();
        mma_stage(acc, sb + (kt % 3) * STAGE_BYTES, wc);
        __syncthreads();
        if (kt + 2 < NKT_X) load_tile(kt + 2, (kt + 2) % 3);
        cp_commit();
    }

#pragma unroll
    for (int i = 0; i < 2; ++i) {
        int row0 = m0 + (wid & 3) * 32 + i * 16 + (lane >> 2);
#pragma unroll
        for (int g = 0; g < 8; ++g) {
            int col = n0 + (wid >> 2) * 64 + g * 8 + (lane & 3) * 2;
            float2 bb = *(const float2*)&b[col];
            *(float2*)&g_vx[(size_t)row0 * GG + col] =
                make_float2(acc[i][g][0] + bb.x, acc[i][g][1] + bb.y);
            *(float2*)&g_vx[(size_t)(row0 + 8) * GG + col] =
                make_float2(acc[i][g][2] + bb.x, acc[i][g][3] + bb.y);
        }
    }
}

// ---------------- gates + state update + output write --------------------------
__global__ void gate_kernel(float* __restrict__ out, int t) {
    int idx = blockIdx.x * 256 + threadIdx.x;
    int n = idx >> 10;
    int j = idx & 1023;
    const float* vr  = g_v  + (size_t)n * GG;
    const float* vxr = g_vx + ((size_t)n * TT + t) * GG;
    float vi = vr[j]        + vxr[j];
    float vf = vr[j + 1024] + vxr[j + 1024];
    float vo = vr[j + 2048] + vxr[j + 2048];
    float vg = vr[j + 3072] + vxr[j + 3072];
    float ig = 1.0f / (1.0f + expf(-vi));
    float fg = 1.0f / (1.0f + expf(-vf));
    float og = 1.0f / (1.0f + expf(-vo));
    float gg = tanhf(vg);
    float c = fg * g_c[idx] + ig * gg;
    float h = og * tanhf(c);
    g_c[idx] = c;
    g_hh[idx] = __float2half(h);
    out[(size_t)n * (TT * HH) + (size_t)t * HH + j] = h;
}

// ---------------- launch ---------------------------------------------------------
extern "C" void kernel_launch(void* const* d_in, const int* in_sizes, int n_in,
                              void* d_out, int out_size) {
    const float* x     = (const float*)d_in[0];   // (N, T, D)
    const float* A     = (const float*)d_in[1];   // (N, H, 4, 4)
    const float* Wx    = (const float*)d_in[2];   // (D, 4H)
    const float* Wh    = (const float*)d_in[3];   // (H, 4H)
    const float* Wattn = (const float*)d_in[4];   // (H, 4H)
    const float* b     = (const float*)d_in[5];   // (4H,)
    float* out = (float*)d_out;                   // (N, T, H)

    cudaFuncSetAttribute(gemm_step, cudaFuncAttributeMaxDynamicSharedMemorySize, GEMM_SMEM);
    cudaFuncSetAttribute(gemm_x,    cudaFuncAttributeMaxDynamicSharedMemorySize, GEMM_SMEM);

    prep_w<<<dim3(KK / 32, GG / 32), dim3(32, 8)>>>(Wx, Wh, Wattn);
    cvt_x<<<(NN * TT * DD) / 1024, 256>>>(x);
    cvt_A<<<(NN * HH * 16) / 1024, 256>>>(A);
    init_kernel<<<(NN * HH) / 256, 256>>>(A);
    gemm_x<<<dim3(GG / 128, (NN * TT) / 128), 256, GEMM_SMEM>>>(b);
    for (int t = 0; t < TT; ++t) {
        attn_kernel<<<NN, 256>>>();
        gemm_step<<<dim3(GG / 128, NN / 128), 256, GEMM_SMEM>>>();
        gate_kernel<<<(NN * HH) / 256, 256>>>(out, t);
    }
}

// round 9
// speedup vs baseline: 2.4701x; 1.1161x over previous
#include <cuda_runtime.h>
#include <cuda_fp16.h>
#include <cstdint>

#define NN 512
#define TT 32
#define DD 1024
#define HH 1024
#define GG 4096   // 4*H
#define KK 3072   // H + H + D

// ---------------- scratch (device globals; no allocation allowed) -------------
__device__ float g_c[NN * HH];
__device__ float g_v[(size_t)NN * GG];
__device__ __align__(256) __half g_vxh[(size_t)NN * TT * GG];  // precomputed x@Wx + b (fp16)
__device__ __align__(256) __half g_hh[NN * HH];       // h (fp16)
__device__ __align__(256) __half g_ah[NN * HH];       // attn (fp16)
__device__ __align__(256) __half g_xh[(size_t)NN * TT * DD];   // x (fp16)
__device__ __align__(256) __half g_Ah[(size_t)NN * HH * 16];   // A (fp16)
__device__ __align__(256) __half g_wt[(size_t)GG * KK];        // W^T fp16 [4096][3072]

// ---------------- small helpers ------------------------------------------------
__device__ __forceinline__ uint32_t smem_u32(const void* p) {
    uint32_t a;
    asm("{ .reg .u64 t; cvta.to.shared.u64 t, %1; cvt.u32.u64 %0, t; }" : "=r"(a) : "l"(p));
    return a;
}
__device__ __forceinline__ void cp16(uint32_t dst, const void* src) {
    asm volatile("cp.async.cg.shared.global [%0], [%1], 16;" :: "r"(dst), "l"(src));
}
__device__ __forceinline__ void cp_commit() { asm volatile("cp.async.commit_group;" ::: "memory"); }
template <int N> __device__ __forceinline__ void cp_wait() {
    asm volatile("cp.async.wait_group %0;" :: "n"(N) : "memory");
}
__device__ __forceinline__ void ldsm4(uint32_t& r0, uint32_t& r1, uint32_t& r2, uint32_t& r3,
                                      uint32_t addr) {
    asm volatile("ldmatrix.sync.aligned.m8n8.x4.shared.b16 {%0,%1,%2,%3}, [%4];"
                 : "=r"(r0), "=r"(r1), "=r"(r2), "=r"(r3) : "r"(addr));
}
__device__ __forceinline__ void mma16816(float* d, const uint32_t* a, uint32_t b0, uint32_t b1) {
    asm volatile(
        "mma.sync.aligned.m16n8k16.row.col.f32.f16.f16.f32 "
        "{%0,%1,%2,%3}, {%4,%5,%6,%7}, {%8,%9}, {%0,%1,%2,%3};"
        : "+f"(d[0]), "+f"(d[1]), "+f"(d[2]), "+f"(d[3])
        : "r"(a[0]), "r"(a[1]), "r"(a[2]), "r"(a[3]), "r"(b0), "r"(b1));
}

// ---------------- one-time prep kernels ----------------------------------------
// Transpose + fp16 round of [Wh; Wattn; Wx] (3072 x 4096) -> W^T (4096 x 3072)
__global__ void prep_w(const float* __restrict__ Wx, const float* __restrict__ Wh,
                       const float* __restrict__ Wattn) {
    __shared__ float tile[32][33];
    int k0 = blockIdx.x * 32, n0 = blockIdx.y * 32;
#pragma unroll
    for (int dy = 0; dy < 32; dy += 8) {
        int k = k0 + threadIdx.y + dy;
        int n = n0 + threadIdx.x;
        const float* W;
        int kk = k;
        if (k < 1024)       { W = Wh; }
        else if (k < 2048)  { W = Wattn; kk = k - 1024; }
        else                { W = Wx;    kk = k - 2048; }
        tile[threadIdx.y + dy][threadIdx.x] = W[(size_t)kk * GG + n];
    }
    __syncthreads();
#pragma unroll
    for (int dy = 0; dy < 32; dy += 8) {
        int n = n0 + threadIdx.y + dy;
        int k = k0 + threadIdx.x;
        g_wt[(size_t)n * KK + k] = __float2half(tile[threadIdx.x][threadIdx.y + dy]);
    }
}

// fp32 -> fp16 conversions (device globals referenced in device code only)
__global__ void cvt_x(const float* __restrict__ src) {
    size_t i = (size_t)blockIdx.x * 256 + threadIdx.x;
    float4 f = ((const float4*)src)[i];
    union { uint2 u; __half2 h[2]; } U;
    U.h[0] = __floats2half2_rn(f.x, f.y);
    U.h[1] = __floats2half2_rn(f.z, f.w);
    ((uint2*)g_xh)[i] = U.u;
}
__global__ void cvt_A(const float* __restrict__ src) {
    size_t i = (size_t)blockIdx.x * 256 + threadIdx.x;
    float4 f = ((const float4*)src)[i];
    union { uint2 u; __half2 h[2]; } U;
    U.h[0] = __floats2half2_rn(f.x, f.y);
    U.h[1] = __floats2half2_rn(f.z, f.w);
    ((uint2*)g_Ah)[i] = U.u;
}

// ---------------- init: h0 = c0 = mean over the 16 spatial cells ---------------
__global__ void init_kernel(const float* __restrict__ A) {
    int idx = blockIdx.x * 256 + threadIdx.x;
    const float4* a4 = (const float4*)(A + (size_t)idx * 16);
    float4 a0 = a4[0], a1 = a4[1], a2 = a4[2], a3 = a4[3];
    float s = ((a0.x + a0.y) + (a0.z + a0.w)) + ((a1.x + a1.y) + (a1.z + a1.w))
            + ((a2.x + a2.y) + (a2.z + a2.w)) + ((a3.x + a3.y) + (a3.z + a3.w));
    s *= (1.0f / 16.0f);
    g_c[idx] = s;
    g_hh[idx] = __float2half(s);
}

// ---------------- attention over 16 spatial cells (A register-cached) ----------
__global__ __launch_bounds__(256) void attn_kernel() {
    int n = blockIdx.x;
    const __half* Af = g_Ah + (size_t)n * HH * 16;
    const __half* hp = g_hh + (size_t)n * HH;
    int tid = threadIdx.x;

    // register-cache 4 rows of A (each 16 fp16 = two uint4) + h values
    union Row { uint4 u[2]; __half2 h[8]; };
    Row ar[4];
    float hv[4];
#pragma unroll
    for (int r = 0; r < 4; ++r) {
        int j = tid + r * 256;
        ar[r].u[0] = *(const uint4*)(Af + (size_t)j * 16);
        ar[r].u[1] = *(const uint4*)(Af + (size_t)j * 16 + 8);
        hv[r] = __half2float(hp[j]);
    }

    float part[16];
#pragma unroll
    for (int k = 0; k < 16; ++k) part[k] = 0.0f;
#pragma unroll
    for (int r = 0; r < 4; ++r) {
#pragma unroll
        for (int q = 0; q < 8; ++q) {
            float2 f = __half22float2(ar[r].h[q]);
            part[2 * q]     += hv[r] * f.x;
            part[2 * q + 1] += hv[r] * f.y;
        }
    }
#pragma unroll
    for (int k = 0; k < 16; ++k)
#pragma unroll
        for (int off = 16; off; off >>= 1)
            part[k] += __shfl_xor_sync(0xffffffffu, part[k], off);

    __shared__ float sred[8][16];
    __shared__ float sM[16];
    int warp = tid >> 5, lane = tid & 31;
    if (lane == 0) {
#pragma unroll
        for (int k = 0; k < 16; ++k) sred[warp][k] = part[k];
    }
    __syncthreads();

    if (tid < 32) {
        int k = lane & 15;
        float s = 0.0f;
#pragma unroll
        for (int w = 0; w < 8; ++w) s += sred[w][k];
        s *= (1.0f / 32.0f);                         // / sqrt(H)
        float m = s;
#pragma unroll
        for (int off = 8; off; off >>= 1) m = fmaxf(m, __shfl_xor_sync(0xffffffffu, m, off));
        float e = expf(s - m);
        float sum = e;
#pragma unroll
        for (int off = 8; off; off >>= 1) sum += __shfl_xor_sync(0xffffffffu, sum, off);
        if (lane < 16) sM[lane] = e / sum;
    }
    __syncthreads();

#pragma unroll
    for (int r = 0; r < 4; ++r) {
        int j = tid + r * 256;
        float s = 0.0f;
#pragma unroll
        for (int q = 0; q < 8; ++q) {
            float2 f = __half22float2(ar[r].h[q]);
            s += f.x * sM[2 * q] + f.y * sM[2 * q + 1];
        }
        g_ah[(size_t)n * HH + j] = __float2half(s);
    }
}

// ---------------- shared GEMM machinery (fp16 1-pass, K=128 per stage) ----------
#define STAGE_BYTES 65536
#define A_S0 0
#define A_S1 16384
#define B_S0 32768
#define B_S1 49152
#define GEMM_SMEM (3 * STAGE_BYTES)

struct WarpCtx {
    uint32_t swb, aRow, aHalf, bRow, bHalf;
};
__device__ __forceinline__ WarpCtx warp_ctx(int wm, int wn, int lane) {
    WarpCtx c;
    c.swb   = (lane & 7) << 4;
    c.aRow  = (uint32_t)(wm * 32 + (lane & 15)) * 128;
    c.aHalf = (uint32_t)(lane >> 4);
    c.bRow  = (uint32_t)(wn * 64 + (lane & 7) + ((lane >> 4) << 3)) * 128;
    c.bHalf = (uint32_t)((lane >> 3) & 1);
    return c;
}

// one 64-K slab: A[128x64] @ a_base, B[128x64] @ b_base (SW64-row swizzled tiles)
__device__ __forceinline__ void mma_slab(float acc[2][8][4], uint32_t a_base, uint32_t b_base,
                                         const WarpCtx& c) {
#pragma unroll
    for (int q = 0; q < 4; ++q) {
        uint32_t aChunk = ((2 * q + c.aHalf) << 4) ^ c.swb;
        uint32_t bChunk = ((2 * q + c.bHalf) << 4) ^ c.swb;
        uint32_t af[2][4];
#pragma unroll
        for (int i = 0; i < 2; ++i) {
            uint32_t ao = c.aRow + (uint32_t)i * 2048 + aChunk;
            ldsm4(af[i][0], af[i][1], af[i][2], af[i][3], a_base + ao);
        }
        uint32_t bf[4][4];
#pragma unroll
        for (int p = 0; p < 4; ++p) {
            uint32_t bo = c.bRow + (uint32_t)p * 2048 + bChunk;
            ldsm4(bf[p][0], bf[p][1], bf[p][2], bf[p][3], b_base + bo);
        }
#pragma unroll
        for (int i = 0; i < 2; ++i)
#pragma unroll
            for (int g = 0; g < 8; ++g) {
                mma16816(acc[i][g], af[i],
                         bf[g >> 1][(g & 1) * 2], bf[g >> 1][(g & 1) * 2 + 1]);
            }
    }
}

// ---------------- per-step GEMM: v = [h | attn] @ [Wh; Wattn]^T  (K=2048) -------
#define NKT_S 16   // 16 stages x K128
__global__ __launch_bounds__(256, 1) void gemm_step() {
    extern __shared__ char dynsmem[];
    uint32_t sb = smem_u32(dynsmem);
    const int tid = threadIdx.x;
    const int wid = tid >> 5, lane = tid & 31;
    const WarpCtx wc = warp_ctx(wid & 3, wid >> 2, lane);
    const int m0 = blockIdx.y * 128;
    const int n0 = blockIdx.x * 128;

    float acc[2][8][4];
#pragma unroll
    for (int i = 0; i < 2; ++i)
#pragma unroll
        for (int g = 0; g < 8; ++g)
#pragma unroll
            for (int r = 0; r < 4; ++r) acc[i][g][r] = 0.0f;

    auto load_tile = [&](int kt, int stage) {   // kt indexes K128 chunks
        uint32_t base = sb + stage * STAGE_BYTES;
        const __half* ap = (kt < 8) ? g_hh : g_ah;
        size_t akoff = (size_t)(kt & 7) * 128;
        size_t bkoff = (size_t)kt * 128;
#pragma unroll
        for (int slab = 0; slab < 2; ++slab) {
            uint32_t abase = base + (slab ? A_S1 : A_S0);
            uint32_t bbase = base + (slab ? B_S1 : B_S0);
            size_t ks = (size_t)slab * 64;
#pragma unroll
            for (int i = 0; i < 4; ++i) {
                int cidx = tid + i * 256;
                int row = cidx >> 3, c16 = cidx & 7;
                uint32_t off = row * 128 + c16 * 16;
                uint32_t sw = off ^ ((off >> 3) & 0x70);
                size_t aoff = (size_t)(m0 + row) * HH + akoff + ks + (size_t)c16 * 8;
                size_t boff = (size_t)(n0 + row) * KK + bkoff + ks + (size_t)c16 * 8;
                cp16(abase + sw, ap + aoff);
                cp16(bbase + sw, g_wt + boff);
            }
        }
    };

    load_tile(0, 0); cp_commit();
    load_tile(1, 1); cp_commit();

    for (int kt = 0; kt < NKT_S; ++kt) {
        cp_wait<1>();
        __syncthreads();
        uint32_t base = sb + (kt % 3) * STAGE_BYTES;
        mma_slab(acc, base + A_S0, base + B_S0, wc);
        mma_slab(acc, base + A_S1, base + B_S1, wc);
        __syncthreads();
        if (kt + 2 < NKT_S) load_tile(kt + 2, (kt + 2) % 3);
        cp_commit();
    }

#pragma unroll
    for (int i = 0; i < 2; ++i) {
        int row0 = m0 + (wid & 3) * 32 + i * 16 + (lane >> 2);
#pragma unroll
        for (int g = 0; g < 8; ++g) {
            int col = n0 + (wid >> 2) * 64 + g * 8 + (lane & 3) * 2;
            *(float2*)&g_v[(size_t)row0 * GG + col]       = make_float2(acc[i][g][0], acc[i][g][1]);
            *(float2*)&g_v[(size_t)(row0 + 8) * GG + col] = make_float2(acc[i][g][2], acc[i][g][3]);
        }
    }
}

// ---------------- one-time GEMM: vx = X @ Wx^T + b  (M=16384, K=1024) -----------
#define NKT_X 8    // 8 stages x K128
__global__ __launch_bounds__(256, 1) void gemm_x(const float* __restrict__ b) {
    extern __shared__ char dynsmem[];
    uint32_t sb = smem_u32(dynsmem);
    const int tid = threadIdx.x;
    const int wid = tid >> 5, lane = tid & 31;
    const WarpCtx wc = warp_ctx(wid & 3, wid >> 2, lane);
    const int m0 = blockIdx.y * 128;
    const int n0 = blockIdx.x * 128;

    float acc[2][8][4];
#pragma unroll
    for (int i = 0; i < 2; ++i)
#pragma unroll
        for (int g = 0; g < 8; ++g)
#pragma unroll
            for (int r = 0; r < 4; ++r) acc[i][g][r] = 0.0f;

    auto load_tile = [&](int kt, int stage) {
        uint32_t base = sb + stage * STAGE_BYTES;
        size_t akoff = (size_t)kt * 128;
        size_t bkoff = 2048 + (size_t)kt * 128;
#pragma unroll
        for (int slab = 0; slab < 2; ++slab) {
            uint32_t abase = base + (slab ? A_S1 : A_S0);
            uint32_t bbase = base + (slab ? B_S1 : B_S0);
            size_t ks = (size_t)slab * 64;
#pragma unroll
            for (int i = 0; i < 4; ++i) {
                int cidx = tid + i * 256;
                int row = cidx >> 3, c16 = cidx & 7;
                uint32_t off = row * 128 + c16 * 16;
                uint32_t sw = off ^ ((off >> 3) & 0x70);
                size_t aoff = (size_t)(m0 + row) * DD + akoff + ks + (size_t)c16 * 8;
                size_t boff = (size_t)(n0 + row) * KK + bkoff + ks + (size_t)c16 * 8;
                cp16(abase + sw, g_xh + aoff);
                cp16(bbase + sw, g_wt + boff);
            }
        }
    };

    load_tile(0, 0); cp_commit();
    load_tile(1, 1); cp_commit();

    for (int kt = 0; kt < NKT_X; ++kt) {
        cp_wait<1>();
        __syncthreads();
        uint32_t base = sb + (kt % 3) * STAGE_BYTES;
        mma_slab(acc, base + A_S0, base + B_S0, wc);
        mma_slab(acc, base + A_S1, base + B_S1, wc);
        __syncthreads();
        if (kt + 2 < NKT_X) load_tile(kt + 2, (kt + 2) % 3);
        cp_commit();
    }

#pragma unroll
    for (int i = 0; i < 2; ++i) {
        int row0 = m0 + (wid & 3) * 32 + i * 16 + (lane >> 2);
#pragma unroll
        for (int g = 0; g < 8; ++g) {
            int col = n0 + (wid >> 2) * 64 + g * 8 + (lane & 3) * 2;
            float2 bb = *(const float2*)&b[col];
            *(__half2*)&g_vxh[(size_t)row0 * GG + col] =
                __floats2half2_rn(acc[i][g][0] + bb.x, acc[i][g][1] + bb.y);
            *(__half2*)&g_vxh[(size_t)(row0 + 8) * GG + col] =
                __floats2half2_rn(acc[i][g][2] + bb.x, acc[i][g][3] + bb.y);
        }
    }
}

// ---------------- gates + state update + output write (2 j per thread) ---------
__global__ void gate_kernel(float* __restrict__ out, int t) {
    int idx2 = blockIdx.x * 256 + threadIdx.x;       // pair index
    int n = idx2 >> 9;
    int jj = (idx2 & 511) * 2;
    const float* vr  = g_v + (size_t)n * GG;
    const __half* vxr = g_vxh + ((size_t)n * TT + t) * GG;

    float2 vi2 = *(const float2*)&vr[jj];
    float2 vf2 = *(const float2*)&vr[jj + 1024];
    float2 vo2 = *(const float2*)&vr[jj + 2048];
    float2 vg2 = *(const float2*)&vr[jj + 3072];
    float2 xi2 = __half22float2(*(const __half2*)&vxr[jj]);
    float2 xf2 = __half22float2(*(const __half2*)&vxr[jj + 1024]);
    float2 xo2 = __half22float2(*(const __half2*)&vxr[jj + 2048]);
    float2 xg2 = __half22float2(*(const __half2*)&vxr[jj + 3072]);

    size_t idx = (size_t)n * HH + jj;
    float2 c2 = *(const float2*)&g_c[idx];
    float h01[2], c01[2];
#pragma unroll
    for (int u = 0; u < 2; ++u) {
        float vi = (u ? vi2.y + xi2.y : vi2.x + xi2.x);
        float vf = (u ? vf2.y + xf2.y : vf2.x + xf2.x);
        float vo = (u ? vo2.y + xo2.y : vo2.x + xo2.x);
        float vg = (u ? vg2.y + xg2.y : vg2.x + xg2.x);
        float ig = 1.0f / (1.0f + expf(-vi));
        float fg = 1.0f / (1.0f + expf(-vf));
        float og = 1.0f / (1.0f + expf(-vo));
        float gg = tanhf(vg);
        float c = fg * (u ? c2.y : c2.x) + ig * gg;
        c01[u] = c;
        h01[u] = og * tanhf(c);
    }
    *(float2*)&g_c[idx] = make_float2(c01[0], c01[1]);
    *(__half2*)&g_hh[idx] = __floats2half2_rn(h01[0], h01[1]);
    *(float2*)&out[(size_t)n * (TT * HH) + (size_t)t * HH + jj] = make_float2(h01[0], h01[1]);
}

// ---------------- launch ---------------------------------------------------------
extern "C" void kernel_launch(void* const* d_in, const int* in_sizes, int n_in,
                              void* d_out, int out_size) {
    const float* x     = (const float*)d_in[0];   // (N, T, D)
    const float* A     = (const float*)d_in[1];   // (N, H, 4, 4)
    const float* Wx    = (const float*)d_in[2];   // (D, 4H)
    const float* Wh    = (const float*)d_in[3];   // (H, 4H)
    const float* Wattn = (const float*)d_in[4];   // (H, 4H)
    const float* b     = (const float*)d_in[5];   // (4H,)
    float* out = (float*)d_out;                   // (N, T, H)

    cudaFuncSetAttribute(gemm_step, cudaFuncAttributeMaxDynamicSharedMemorySize, GEMM_SMEM);
    cudaFuncSetAttribute(gemm_x,    cudaFuncAttributeMaxDynamicSharedMemorySize, GEMM_SMEM);

    prep_w<<<dim3(KK / 32, GG / 32), dim3(32, 8)>>>(Wx, Wh, Wattn);
    cvt_x<<<(NN * TT * DD) / 1024, 256>>>(x);
    cvt_A<<<(NN * HH * 16) / 1024, 256>>>(A);
    init_kernel<<<(NN * HH) / 256, 256>>>(A);
    gemm_x<<<dim3(GG / 128, (NN * TT) / 128), 256, GEMM_SMEM>>>(b);
    for (int t = 0; t < TT; ++t) {
        attn_kernel<<<NN, 256>>>();
        gemm_step<<<dim3(GG / 128, NN / 128), 256, GEMM_SMEM>>>();
        gate_kernel<<<(NN * HH) / 512, 256>>>(out, t);
    }
}